// round 1
// baseline (speedup 1.0000x reference)
#include <cuda_runtime.h>

#define NB 8
#define NG 512
#define NT 1024
#define NK 5
#define NC 3
#define TPB 256
#define WARPS_PER_BLOCK 8   // one t per warp

__device__ __forceinline__ float ex2f(float x) {
    float y;
    asm("ex2.approx.ftz.f32 %0, %1;" : "=f"(y) : "f"(x));
    return y;
}

__global__ __launch_bounds__(TPB)
void final_layer_kernel(const float* __restrict__ x_grid,
                        const float* __restrict__ h_grid,
                        const float* __restrict__ target_x,
                        const float* __restrict__ sigma,
                        const float* __restrict__ g_w,
                        const float* __restrict__ g_b,
                        float* __restrict__ out)
{
    // Transposed staging: [item][g] so lanes (consecutive g) are conflict-free.
    __shared__ float sx[NC][NG];          // x_grid for this batch
    __shared__ float sh[NK * NC][NG];     // h_grid * g_w[k]

    const int b    = blockIdx.y;
    const int tid  = threadIdx.x;
    const int warp = tid >> 5;
    const int lane = tid & 31;
    const int t    = blockIdx.x * WARPS_PER_BLOCK + warp;

    // ---- stage x_grid (b, g, c) -> sx[c][g] ----
    const float* xg = x_grid + b * NG * NC;
    for (int idx = tid; idx < NG * NC; idx += TPB) {
        int g = idx / NC;
        int c = idx - g * NC;
        sx[c][g] = xg[idx];
    }

    // ---- stage h_grid (b, g, k, c) * g_w[k] -> sh[k*3+c][g] ----
    float gw[NK];
    #pragma unroll
    for (int k = 0; k < NK; k++) gw[k] = g_w[k];

    const float* hg = h_grid + b * NG * NK * NC;
    for (int idx = tid; idx < NG * NK * NC; idx += TPB) {
        int g = idx / (NK * NC);
        int r = idx - g * (NK * NC);     // r = k*NC + c
        sh[r][g] = hg[idx] * gw[r / NC];
    }

    // ---- per-thread exponent coefficients: a2[k][c] = -0.5*log2(e)/scale^2 ----
    float a2[NK][NC];
    #pragma unroll
    for (int k = 0; k < NK; k++) {
        #pragma unroll
        for (int c = 0; c < NC; c++) {
            float s   = __expf(sigma[k * NC + c]) + 1e-6f;
            float inv = 1.0f / s;
            a2[k][c]  = -0.5f * 1.4426950408889634f * inv * inv;
        }
    }

    // target point for this warp's t (broadcast load)
    const float t0 = target_x[(b * NT + t) * NC + 0];
    const float t1 = target_x[(b * NT + t) * NC + 1];
    const float t2 = target_x[(b * NT + t) * NC + 2];

    __syncthreads();

    float acc0 = 0.f, acc1 = 0.f, acc2 = 0.f;

    #pragma unroll 4
    for (int i = 0; i < NG / 32; i++) {
        const int g = lane + 32 * i;
        const float d0 = sx[0][g] - t0; const float u0 = d0 * d0;
        const float d1 = sx[1][g] - t1; const float u1 = d1 * d1;
        const float d2 = sx[2][g] - t2; const float u2 = d2 * d2;
        #pragma unroll
        for (int k = 0; k < NK; k++) {
            acc0 += sh[k * NC + 0][g] * ex2f(a2[k][0] * u0);
            acc1 += sh[k * NC + 1][g] * ex2f(a2[k][1] * u1);
            acc2 += sh[k * NC + 2][g] * ex2f(a2[k][2] * u2);
        }
    }

    // ---- warp reduction over g-lanes ----
    #pragma unroll
    for (int off = 16; off; off >>= 1) {
        acc0 += __shfl_xor_sync(0xffffffffu, acc0, off);
        acc1 += __shfl_xor_sync(0xffffffffu, acc1, off);
        acc2 += __shfl_xor_sync(0xffffffffu, acc2, off);
    }

    if (lane == 0) {
        const float bb = g_b[0];
        float* o = out + (b * NT + t) * NC;
        o[0] = acc0 + bb;
        o[1] = acc1 + bb;
        o[2] = acc2 + bb;
    }
}

extern "C" void kernel_launch(void* const* d_in, const int* in_sizes, int n_in,
                              void* d_out, int out_size)
{
    const float* x_grid   = (const float*)d_in[0];  // (8, 512, 3)
    const float* h_grid   = (const float*)d_in[1];  // (8, 512, 5, 3)
    const float* target_x = (const float*)d_in[2];  // (8, 1024, 3)
    const float* sigma    = (const float*)d_in[3];  // (5, 3)
    const float* g_w      = (const float*)d_in[4];  // (1, 5)
    const float* g_b      = (const float*)d_in[5];  // (1,)
    float* out = (float*)d_out;                     // (8, 1024, 3)

    dim3 grid(NT / WARPS_PER_BLOCK, NB);
    final_layer_kernel<<<grid, TPB>>>(x_grid, h_grid, target_x, sigma, g_w, g_b, out);
}

// round 2
// speedup vs baseline: 2.4946x; 2.4946x over previous
#include <cuda_runtime.h>
#include <math.h>

#define NB 8
#define NG 512
#define NT 1024
#define NK 5
#define NC 3
#define TPB 256
#define WPB 8                 // warps per block
#define TGT_PER_WARP 2
#define T_PER_BLOCK (WPB * TGT_PER_WARP)   // 16 targets per block

__device__ __forceinline__ float ex2f(float x) {
    float y;
    asm("ex2.approx.ftz.f32 %0, %1;" : "=f"(y) : "f"(x));
    return y;
}

__device__ __forceinline__ float warp_sum(float v) {
    #pragma unroll
    for (int off = 16; off; off >>= 1)
        v += __shfl_xor_sync(0xffffffffu, v, off);
    return v;
}

__global__ __launch_bounds__(TPB)
void final_layer_kernel(const float* __restrict__ x_grid,
                        const float* __restrict__ h_grid,
                        const float* __restrict__ target_x,
                        const float* __restrict__ sigma,
                        const float* __restrict__ g_w,
                        const float* __restrict__ g_b,
                        float* __restrict__ out)
{
    __shared__ float sx[NC][NG];        // coords (scaled in fast path)
    __shared__ float sh[NK * NC][NG];   // fast path: rows 0..2 = hsum; slow: 15 rows

    const int b    = blockIdx.y;
    const int tid  = threadIdx.x;
    const int warp = tid >> 5;
    const int lane = tid & 31;

    // per-(k,c) exponent coefficient a2 = -0.5*log2(e)/scale^2
    float a2[NK][NC];
    #pragma unroll
    for (int k = 0; k < NK; k++)
        #pragma unroll
        for (int c = 0; c < NC; c++) {
            float s   = __expf(sigma[k * NC + c]) + 1e-6f;
            float inv = 1.0f / s;
            a2[k][c]  = -0.5f * 1.4426950408889634f * inv * inv;
        }

    // block-uniform check: per channel, all k share the same scale?
    bool uni = true;
    #pragma unroll
    for (int k = 1; k < NK; k++)
        #pragma unroll
        for (int c = 0; c < NC; c++)
            uni = uni && (a2[k][c] == a2[0][c]);

    float gw[NK];
    #pragma unroll
    for (int k = 0; k < NK; k++) gw[k] = g_w[k];

    const float* xg = x_grid + b * NG * NC;
    const float* hg = h_grid + b * NG * NK * NC;
    const int tbase = blockIdx.x * T_PER_BLOCK + warp * TGT_PER_WARP;
    const float bb  = g_b[0];

    if (uni) {
        // ============ FAST PATH: one scale per channel ============
        float r0 = sqrtf(-a2[0][0]);
        float r1 = sqrtf(-a2[0][1]);
        float r2 = sqrtf(-a2[0][2]);

        // stage scaled coords: sx[c][g] = r_c * x[g,c]
        for (int idx = tid; idx < NG * NC; idx += TPB) {
            int g = idx / NC;
            int c = idx - g * NC;
            float rc = (c == 0) ? r0 : (c == 1) ? r1 : r2;
            sx[c][g] = xg[idx] * rc;
        }
        // stage hsum[c][g] = sum_k gw[k] * h[g,k,c]
        for (int j = tid; j < NG * NC; j += TPB) {
            int g = j / NC;
            int c = j - g * NC;
            const float* hp = hg + g * NK * NC + c;
            float s = 0.f;
            #pragma unroll
            for (int k = 0; k < NK; k++) s += gw[k] * hp[k * NC];
            sh[c][g] = s;
        }
        __syncthreads();

        // two targets per warp
        const float* tpA = target_x + (b * NT + tbase) * NC;
        const float tA0 = tpA[0] * r0, tA1 = tpA[1] * r1, tA2 = tpA[2] * r2;
        const float tB0 = tpA[3] * r0, tB1 = tpA[4] * r1, tB2 = tpA[5] * r2;

        float aA0 = 0.f, aA1 = 0.f, aA2 = 0.f;
        float aB0 = 0.f, aB1 = 0.f, aB2 = 0.f;

        #pragma unroll
        for (int i = 0; i < NG / 32; i++) {
            const int g = lane + 32 * i;
            const float x0 = sx[0][g], x1 = sx[1][g], x2 = sx[2][g];
            const float h0 = sh[0][g], h1 = sh[1][g], h2 = sh[2][g];

            float d;
            d = x0 - tA0; aA0 += h0 * ex2f(d * (-d));
            d = x1 - tA1; aA1 += h1 * ex2f(d * (-d));
            d = x2 - tA2; aA2 += h2 * ex2f(d * (-d));
            d = x0 - tB0; aB0 += h0 * ex2f(d * (-d));
            d = x1 - tB1; aB1 += h1 * ex2f(d * (-d));
            d = x2 - tB2; aB2 += h2 * ex2f(d * (-d));
        }

        aA0 = warp_sum(aA0); aA1 = warp_sum(aA1); aA2 = warp_sum(aA2);
        aB0 = warp_sum(aB0); aB1 = warp_sum(aB1); aB2 = warp_sum(aB2);

        if (lane == 0) {
            float* o = out + (b * NT + tbase) * NC;
            o[0] = aA0 + bb; o[1] = aA1 + bb; o[2] = aA2 + bb;
            o[3] = aB0 + bb; o[4] = aB1 + bb; o[5] = aB2 + bb;
        }
    } else {
        // ============ GENERAL PATH: per-(k,c) scales ============
        for (int idx = tid; idx < NG * NC; idx += TPB) {
            int g = idx / NC;
            int c = idx - g * NC;
            sx[c][g] = xg[idx];
        }
        for (int idx = tid; idx < NG * NK * NC; idx += TPB) {
            int g = idx / (NK * NC);
            int r = idx - g * (NK * NC);      // r = k*NC + c
            sh[r][g] = hg[idx] * gw[r / NC];
        }
        __syncthreads();

        const float* tpA = target_x + (b * NT + tbase) * NC;
        const float tA0 = tpA[0], tA1 = tpA[1], tA2 = tpA[2];
        const float tB0 = tpA[3], tB1 = tpA[4], tB2 = tpA[5];

        float aA0 = 0.f, aA1 = 0.f, aA2 = 0.f;
        float aB0 = 0.f, aB1 = 0.f, aB2 = 0.f;

        #pragma unroll 4
        for (int i = 0; i < NG / 32; i++) {
            const int g = lane + 32 * i;
            const float x0 = sx[0][g], x1 = sx[1][g], x2 = sx[2][g];
            const float uA0 = (x0 - tA0) * (x0 - tA0);
            const float uA1 = (x1 - tA1) * (x1 - tA1);
            const float uA2 = (x2 - tA2) * (x2 - tA2);
            const float uB0 = (x0 - tB0) * (x0 - tB0);
            const float uB1 = (x1 - tB1) * (x1 - tB1);
            const float uB2 = (x2 - tB2) * (x2 - tB2);
            #pragma unroll
            for (int k = 0; k < NK; k++) {
                const float h0 = sh[k * NC + 0][g];
                const float h1 = sh[k * NC + 1][g];
                const float h2 = sh[k * NC + 2][g];
                aA0 += h0 * ex2f(a2[k][0] * uA0);
                aA1 += h1 * ex2f(a2[k][1] * uA1);
                aA2 += h2 * ex2f(a2[k][2] * uA2);
                aB0 += h0 * ex2f(a2[k][0] * uB0);
                aB1 += h1 * ex2f(a2[k][1] * uB1);
                aB2 += h2 * ex2f(a2[k][2] * uB2);
            }
        }

        aA0 = warp_sum(aA0); aA1 = warp_sum(aA1); aA2 = warp_sum(aA2);
        aB0 = warp_sum(aB0); aB1 = warp_sum(aB1); aB2 = warp_sum(aB2);

        if (lane == 0) {
            float* o = out + (b * NT + tbase) * NC;
            o[0] = aA0 + bb; o[1] = aA1 + bb; o[2] = aA2 + bb;
            o[3] = aB0 + bb; o[4] = aB1 + bb; o[5] = aB2 + bb;
        }
    }
}

extern "C" void kernel_launch(void* const* d_in, const int* in_sizes, int n_in,
                              void* d_out, int out_size)
{
    const float* x_grid   = (const float*)d_in[0];  // (8, 512, 3)
    const float* h_grid   = (const float*)d_in[1];  // (8, 512, 5, 3)
    const float* target_x = (const float*)d_in[2];  // (8, 1024, 3)
    const float* sigma    = (const float*)d_in[3];  // (5, 3)
    const float* g_w      = (const float*)d_in[4];  // (1, 5)
    const float* g_b      = (const float*)d_in[5];  // (1,)
    float* out = (float*)d_out;                     // (8, 1024, 3)

    dim3 grid(NT / T_PER_BLOCK, NB);
    final_layer_kernel<<<grid, TPB>>>(x_grid, h_grid, target_x, sigma, g_w, g_b, out);
}

// round 3
// speedup vs baseline: 2.6304x; 1.0544x over previous
#include <cuda_runtime.h>
#include <math.h>

#define NB 8
#define NG 512
#define NT 1024
#define NK 5
#define NC 3

#define TPB 256
#define NCHUNK 32
#define CHUNK_G (NG / NCHUNK)   // 16
#define TGRP (NT / TPB)         // 4

// scratch (device globals: allocation-free per harness rules)
__device__ float d_pre[NB * NG * 6];   // [b][g][{x0',x1',x2',h0,h1,h2}]
__device__ float d_ts[NB * NT * NC];   // prescaled (or raw if !uni) targets
__device__ float d_a2[NK * NC];        // -0.5*log2(e)/scale^2
__device__ int   d_uni;

__device__ __forceinline__ float ex2f(float x) {
    float y;
    asm("ex2.approx.ftz.f32 %0, %1;" : "=f"(y) : "f"(x));
    return y;
}

// ---------------- prep: coefficients + prescale + hsum + out init ----------------
__global__ __launch_bounds__(TPB)
void prep_kernel(const float* __restrict__ x_grid,
                 const float* __restrict__ h_grid,
                 const float* __restrict__ target_x,
                 const float* __restrict__ sigma,
                 const float* __restrict__ g_w,
                 const float* __restrict__ g_b,
                 float* __restrict__ out)
{
    const int gid    = blockIdx.x * TPB + threadIdx.x;
    const int stride = gridDim.x * TPB;

    // every thread computes the (tiny) coefficient set
    float a2[NK][NC];
    #pragma unroll
    for (int k = 0; k < NK; k++)
        #pragma unroll
        for (int c = 0; c < NC; c++) {
            float s   = __expf(sigma[k * NC + c]) + 1e-6f;
            float inv = 1.0f / s;
            a2[k][c]  = -0.5f * 1.4426950408889634f * inv * inv;
        }
    bool uni = true;
    #pragma unroll
    for (int k = 1; k < NK; k++)
        #pragma unroll
        for (int c = 0; c < NC; c++)
            uni = uni && (a2[k][c] == a2[0][c]);

    if (gid == 0) {
        d_uni = uni ? 1 : 0;
        #pragma unroll
        for (int k = 0; k < NK; k++)
            #pragma unroll
            for (int c = 0; c < NC; c++)
                d_a2[k * NC + c] = a2[k][c];
    }

    const float r0 = uni ? sqrtf(-a2[0][0]) : 1.0f;
    const float r1 = uni ? sqrtf(-a2[0][1]) : 1.0f;
    const float r2 = uni ? sqrtf(-a2[0][2]) : 1.0f;

    float gw[NK];
    #pragma unroll
    for (int k = 0; k < NK; k++) gw[k] = g_w[k];

    // precomp per (b,g): scaled coords + hsum (fast path only uses this)
    for (int i = gid; i < NB * NG; i += stride) {
        const float* xp = x_grid + i * NC;
        const float* hp = h_grid + i * NK * NC;
        float h0 = 0.f, h1 = 0.f, h2 = 0.f;
        #pragma unroll
        for (int k = 0; k < NK; k++) {
            h0 += gw[k] * hp[k * NC + 0];
            h1 += gw[k] * hp[k * NC + 1];
            h2 += gw[k] * hp[k * NC + 2];
        }
        float* o = d_pre + i * 6;
        o[0] = xp[0] * r0; o[1] = xp[1] * r1; o[2] = xp[2] * r2;
        o[3] = h0;         o[4] = h1;         o[5] = h2;
    }

    // targets (prescaled when uni, raw otherwise)
    for (int i = gid; i < NB * NT; i += stride) {
        const float* tp = target_x + i * NC;
        float* o = d_ts + i * NC;
        o[0] = tp[0] * r0; o[1] = tp[1] * r1; o[2] = tp[2] * r2;
    }

    // out := bias (atomicAdd accumulates on top)
    const float bb = g_b[0];
    for (int i = gid; i < NB * NT * NC; i += stride)
        out[i] = bb;
}

// ---------------- main: lanes-as-targets, g chunked ----------------
__global__ __launch_bounds__(TPB)
void main_kernel(const float* __restrict__ x_grid,
                 const float* __restrict__ h_grid,
                 const float* __restrict__ g_w,
                 float* __restrict__ out)
{
    __shared__ float sp[CHUNK_G][6];

    const int tid   = threadIdx.x;
    const int b     = blockIdx.z;
    const int chunk = blockIdx.y;
    const int t     = blockIdx.x * TPB + tid;
    const int g0    = chunk * CHUNK_G;
    const int obase = (b * NT + t) * NC;

    const float tt0 = d_ts[obase + 0];
    const float tt1 = d_ts[obase + 1];
    const float tt2 = d_ts[obase + 2];

    float acc0 = 0.f, acc1 = 0.f, acc2 = 0.f;

    if (d_uni) {
        // stage this chunk's precomputed data (96 floats)
        if (tid < CHUNK_G * 6)
            ((float*)sp)[tid] = d_pre[(b * NG + g0) * 6 + tid];
        __syncthreads();

        #pragma unroll 4
        for (int gi = 0; gi < CHUNK_G; gi++) {
            const float x0 = sp[gi][0], x1 = sp[gi][1], x2 = sp[gi][2];
            const float h0 = sp[gi][3], h1 = sp[gi][4], h2 = sp[gi][5];
            float d;
            d = x0 - tt0; acc0 += h0 * ex2f(d * (-d));
            d = x1 - tt1; acc1 += h1 * ex2f(d * (-d));
            d = x2 - tt2; acc2 += h2 * ex2f(d * (-d));
        }
    } else {
        // general path: per-(k,c) scales, direct (warp-uniform, L1/L2-cached) loads
        float a2[NK][NC];
        #pragma unroll
        for (int k = 0; k < NK; k++)
            #pragma unroll
            for (int c = 0; c < NC; c++)
                a2[k][c] = d_a2[k * NC + c];
        float gw[NK];
        #pragma unroll
        for (int k = 0; k < NK; k++) gw[k] = __ldg(&g_w[k]);

        for (int gi = 0; gi < CHUNK_G; gi++) {
            const int g = g0 + gi;
            const float* xp = x_grid + (b * NG + g) * NC;
            const float x0 = __ldg(&xp[0]), x1 = __ldg(&xp[1]), x2 = __ldg(&xp[2]);
            const float u0 = (x0 - tt0) * (x0 - tt0);
            const float u1 = (x1 - tt1) * (x1 - tt1);
            const float u2 = (x2 - tt2) * (x2 - tt2);
            const float* hp = h_grid + ((b * NG + g) * NK) * NC;
            #pragma unroll
            for (int k = 0; k < NK; k++) {
                acc0 += gw[k] * __ldg(&hp[k * NC + 0]) * ex2f(a2[k][0] * u0);
                acc1 += gw[k] * __ldg(&hp[k * NC + 1]) * ex2f(a2[k][1] * u1);
                acc2 += gw[k] * __ldg(&hp[k * NC + 2]) * ex2f(a2[k][2] * u2);
            }
        }
    }

    atomicAdd(&out[obase + 0], acc0);
    atomicAdd(&out[obase + 1], acc1);
    atomicAdd(&out[obase + 2], acc2);
}

extern "C" void kernel_launch(void* const* d_in, const int* in_sizes, int n_in,
                              void* d_out, int out_size)
{
    const float* x_grid   = (const float*)d_in[0];  // (8, 512, 3)
    const float* h_grid   = (const float*)d_in[1];  // (8, 512, 5, 3)
    const float* target_x = (const float*)d_in[2];  // (8, 1024, 3)
    const float* sigma    = (const float*)d_in[3];  // (5, 3)
    const float* g_w      = (const float*)d_in[4];  // (1, 5)
    const float* g_b      = (const float*)d_in[5];  // (1,)
    float* out = (float*)d_out;                     // (8, 1024, 3)

    prep_kernel<<<64, TPB>>>(x_grid, h_grid, target_x, sigma, g_w, g_b, out);

    dim3 grid(TGRP, NCHUNK, NB);   // 4 x 32 x 8 = 1024 blocks
    main_kernel<<<grid, TPB>>>(x_grid, h_grid, g_w, out);
}